// round 7
// baseline (speedup 1.0000x reference)
#include <cuda_runtime.h>
#include <cuda_fp16.h>
#include <cstdint>

#define Bv 16
#define Cv 64
#define Hv 128
#define Wv 128
#define HCv 64

// Pre-baked W image (fp16): [chunk(3)][m(256)][k(64) octet-swizzled] = 96 KB
__device__ __align__(16) uint16_t g_wimg[3 * 256 * 64];
// Pre-split X planes (fp16 hi + fp16 residual lo), layout [b][ic][h][w]
#define XN ((size_t)Bv * Cv * Hv * Wv)
__device__ __align__(16) __half g_xhi[XN];
__device__ __align__(16) __half g_xlo[XN];

// ---- smem map (bytes) ----
// W resident: 3 x 32KB at 0 ; XBUF: 2 x 32KB (hi 16KB + lo 16KB) at 98304
// after mainloop (aliased): gates fp32 [w(128)][260 words] + PS at word 33280
#define XBUF_B   98304
#define GST      260
#define PS_W     33280
#define SMEM_BYTES 163840

extern __shared__ uint32_t smw[];

__device__ __forceinline__ uint32_t smem_u32(const void* p) {
    uint32_t a;
    asm("{ .reg .u64 t; cvta.to.shared.u64 t, %1; cvt.u32.u64 %0, t; }"
        : "=r"(a) : "l"(p));
    return a;
}

__device__ __forceinline__ float rcp_fast(float d) {
    float r;
    asm("rcp.approx.ftz.f32 %0, %1;" : "=f"(r) : "f"(d));
    return r;
}

// paired sigmoid: one RCP for two values
__device__ __forceinline__ void sigmoid2(float& v0, float& v1) {
    float e0 = __expf(-v0);
    float e1 = __expf(-v1);
    float p0 = 1.0f + e0, p1 = 1.0f + e1;
    float r = rcp_fast(p0 * p1);
    v0 = p1 * r;
    v1 = p0 * r;
}
// paired tanh: one RCP for two values
__device__ __forceinline__ void tanh2(float& v0, float& v1) {
    float e0 = __expf(-2.0f * fabsf(v0));
    float e1 = __expf(-2.0f * fabsf(v1));
    float p0 = 1.0f + e0, p1 = 1.0f + e1;
    float r = rcp_fast(p0 * p1);
    float t0 = (1.0f - e0) * p1 * r;
    float t1 = (1.0f - e1) * p0 * r;
    v0 = (v0 < 0.0f) ? -t0 : t0;
    v1 = (v1 < 0.0f) ? -t1 : t1;
}

__device__ __forceinline__ void mma_f16(float* c, const uint32_t* a,
                                        uint32_t b0, uint32_t b1) {
    asm volatile(
        "mma.sync.aligned.m16n8k16.row.col.f32.f16.f16.f32 "
        "{%0,%1,%2,%3}, {%4,%5,%6,%7}, {%8,%9}, {%0,%1,%2,%3};\n"
        : "+f"(c[0]), "+f"(c[1]), "+f"(c[2]), "+f"(c[3])
        : "r"(a[0]), "r"(a[1]), "r"(a[2]), "r"(a[3]), "r"(b0), "r"(b1));
}

#define LDM4(R, addr) \
    asm volatile("ldmatrix.sync.aligned.m8n8.x4.shared.b16 {%0,%1,%2,%3}, [%4];" \
        : "=r"((R)[0]), "=r"((R)[1]), "=r"((R)[2]), "=r"((R)[3]) : "r"(addr))
#define LDM4T(R, addr) \
    asm volatile("ldmatrix.sync.aligned.m8n8.x4.trans.shared.b16 {%0,%1,%2,%3}, [%4];" \
        : "=r"((R)[0]), "=r"((R)[1]), "=r"((R)[2]), "=r"((R)[3]) : "r"(addr))
#define CPA16(dst, src) \
    asm volatile("cp.async.ca.shared.global [%0], [%1], 16;" :: "r"(dst), "l"(src))
#define CPA16Z(dst, src, sz) \
    asm volatile("cp.async.ca.shared.global [%0], [%1], 16, %2;" \
                 :: "r"(dst), "l"(src), "r"(sz))
#define CPA_COMMIT() asm volatile("cp.async.commit_group;" ::: "memory")
#define CPA_WAIT0()  asm volatile("cp.async.wait_group 0;" ::: "memory")

// ---------------------------------------------------------------- prep W image
__global__ void prep_w(const float* __restrict__ wgt) {
    int k = blockIdx.x;
    int m = threadIdx.x;
    float v = wgt[m * 192 + k];
    int c = k >> 6, kl = k & 63, o = kl >> 3, e = kl & 7;
    g_wimg[c * 16384 + m * 64 + (((o ^ (m & 7)) << 3) + e)] =
        __half_as_ushort(__float2half_rn(v));
}

// ---------------------------------------------------------------- prep X planes
// 8 floats per thread -> 8 fp16 hi + 8 fp16 lo (residual)
__global__ void __launch_bounds__(256) prep_x(const float* __restrict__ x) {
    size_t i = ((size_t)blockIdx.x * 256 + threadIdx.x) * 8;
    float4 a = *reinterpret_cast<const float4*>(x + i);
    float4 c = *reinterpret_cast<const float4*>(x + i + 4);
    float vf[8] = {a.x, a.y, a.z, a.w, c.x, c.y, c.z, c.w};
    uint32_t hw[4], lw[4];
#pragma unroll
    for (int j = 0; j < 4; j++) {
        __half2 hh = __float22half2_rn(make_float2(vf[2 * j], vf[2 * j + 1]));
        float2 hf = __half22float2(hh);
        __half2 ll = __float22half2_rn(
            make_float2(vf[2 * j] - hf.x, vf[2 * j + 1] - hf.y));
        hw[j] = *reinterpret_cast<uint32_t*>(&hh);
        lw[j] = *reinterpret_cast<uint32_t*>(&ll);
    }
    *reinterpret_cast<uint4*>(g_xhi + i) = make_uint4(hw[0], hw[1], hw[2], hw[3]);
    *reinterpret_cast<uint4*>(g_xlo + i) = make_uint4(lw[0], lw[1], lw[2], lw[3]);
}

// ---------------------------------------------------------------- fused kernel
// One block per (b,h), 512 threads = 16 warps (4m x 4n), warp tile 64x32.
// W (96KB) smem-resident; X (hi/lo fp16 planes) streamed per 64-k chunk via cp.async.
__global__ void __launch_bounds__(512, 1)
rowlstm_fused(const float* __restrict__ bias, float* __restrict__ out) {
    float* smf = reinterpret_cast<float*>(smw);
    const int tid = threadIdx.x;
    const int lane = tid & 31;
    const int wid = tid >> 5;
    const int mw = wid & 3;
    const int nw = wid >> 2;
    const int r = lane >> 2, cl = lane & 3;
    const int bh = blockIdx.x, b = bh >> 7, h = bh & 127;

    const uint32_t smb = smem_u32(smw);

    // ldmatrix lane params
    const int l7 = lane & 7, l15 = lane & 15, lk = lane >> 4;
    const int krl = l7 + ((lane & 16) >> 1);
    const int wo = (lane >> 3) & 1;

    uint64_t gw, gxh, gxl;
    asm("cvta.to.global.u64 %0, %1;" : "=l"(gw) : "l"((const void*)g_wimg));
    asm("cvta.to.global.u64 %0, %1;" : "=l"(gxh) : "l"((const void*)g_xhi));
    asm("cvta.to.global.u64 %0, %1;" : "=l"(gxl) : "l"((const void*)g_xlo));

    float acc[4][4][4];
#pragma unroll
    for (int mt = 0; mt < 4; mt++)
#pragma unroll
        for (int nt = 0; nt < 4; nt++)
#pragma unroll
            for (int q = 0; q < 4; q++) acc[mt][nt][q] = 0.0f;

// stage X chunk cn into buffer db: per thread 2 granules per plane
#define STAGE_X(cn, db)                                                     \
    do {                                                                    \
        _Pragma("unroll") for (int t = 0; t < 2; t++) {                     \
            int g = t * 512 + tid;                                          \
            int krow = g >> 4;                                              \
            int woct = g & 15;                                              \
            int kg = (cn) * 64 + krow;                                      \
            int ic = kg / 3;                                                \
            int kh = kg - 3 * ic;                                           \
            int hp = h + kh - 2;                                            \
            int sz = (hp >= 0) ? 16 : 0;                                    \
            int hpc = (hp >= 0) ? hp : 0;                                   \
            size_t eoff = (((size_t)(b * Cv + ic) * Hv + hpc) * Wv +        \
                           woct * 8) * 2;                                   \
            uint32_t dst = smb + XBUF_B + (db) * 32768 + krow * 256 +       \
                           ((woct ^ (krow & 7)) << 4);                      \
            CPA16Z(dst, gxh + eoff, sz);                                    \
            CPA16Z(dst + 16384, gxl + eoff, sz);                            \
        }                                                                   \
    } while (0)

    // ---- preamble: W (all 96KB) + X chunk 0
    {
#pragma unroll
        for (int j = 0; j < 12; j++)
            CPA16(smb + tid * 16 + j * 8192, gw + tid * 16 + j * 8192);
        STAGE_X(0, 0);
        CPA_COMMIT();
        CPA_WAIT0();
        __syncthreads();
    }

#pragma unroll
    for (int c = 0; c < 3; c++) {
        const int db = c & 1;
        if (c < 2) {
            STAGE_X(c + 1, db ^ 1);
            CPA_COMMIT();
        }

        const uint32_t a_h = smb + c * 32768 + (mw * 64 + l15) * 128;
        uint32_t bb[2];
#pragma unroll
        for (int np = 0; np < 2; np++) {
            int oct = ((nw * 32 + np * 16) >> 3) + wo;
            bb[np] = smb + XBUF_B + db * 32768 + krl * 256 + ((oct ^ l7) << 4);
        }
#pragma unroll
        for (int ks = 0; ks < 4; ks++) {
            uint32_t Bh[2][4], Bl[2][4];
#pragma unroll
            for (int np = 0; np < 2; np++) {
                LDM4T(Bh[np], bb[np] + ks * 4096);
                LDM4T(Bl[np], bb[np] + ks * 4096 + 16384);
            }
            const uint32_t swA = (uint32_t)(((2 * ks + lk) ^ l7) << 4);
#pragma unroll
            for (int mt = 0; mt < 4; mt++) {
                uint32_t A[4];
                LDM4(A, a_h + mt * 2048 + swA);
#pragma unroll
                for (int nt = 0; nt < 4; nt++) {
                    const int np = nt >> 1, ix = nt & 1;
                    mma_f16(acc[mt][nt], A, Bh[np][ix], Bh[np][2 + ix]);
                }
#pragma unroll
                for (int nt = 0; nt < 4; nt++) {
                    const int np = nt >> 1, ix = nt & 1;
                    mma_f16(acc[mt][nt], A, Bl[np][ix], Bl[np][2 + ix]);
                }
            }
        }

        if (c < 2) {
            CPA_WAIT0();
            __syncthreads();
        }
    }
    __syncthreads();  // stage buffers reusable (gates alias them)

    // ---- epilogue: bias + activation -> gates smem [w][260]
    const bool isg = (mw == 3);
#pragma unroll
    for (int mt = 0; mt < 4; mt++) {
        const int m0 = mw * 64 + mt * 16;
        const float blo = bias[m0 + r];
        const float bhi = bias[m0 + 8 + r];
#pragma unroll
        for (int nt = 0; nt < 4; nt++) {
            const int w0 = nw * 32 + nt * 8 + 2 * cl;
            float v0 = acc[mt][nt][0] + blo;
            float v1 = acc[mt][nt][1] + blo;
            float v2 = acc[mt][nt][2] + bhi;
            float v3 = acc[mt][nt][3] + bhi;
            if (isg) { tanh2(v0, v1); tanh2(v2, v3); }
            else     { sigmoid2(v0, v1); sigmoid2(v2, v3); }
            smf[(size_t)w0 * GST + m0 + r]           = v0;
            smf[(size_t)(w0 + 1) * GST + m0 + r]     = v1;
            smf[(size_t)w0 * GST + m0 + 8 + r]       = v2;
            smf[(size_t)(w0 + 1) * GST + m0 + 8 + r] = v3;
        }
    }
    __syncthreads();

    // ---- LSTM scan: 8 segments of 16 w, parallel linear recurrence
    const int seg = tid >> 6;
    const int hc = tid & 63;
    {
        int gb = seg * 16 * GST + hc;
        float c = 0.0f, P = 1.0f;
#pragma unroll 8
        for (int j = 0; j < 16; j++) {
            float iv = smf[gb];
            float fv = smf[gb + 64];
            float gv = smf[gb + 192];
            c = fmaf(fv, c, iv * gv);
            P *= fv;
            smf[gb + 64] = c;
            smf[gb + 192] = P;
            gb += GST;
        }
        smf[PS_W + (seg * 64 + hc) * 2] = P;
        smf[PS_W + (seg * 64 + hc) * 2 + 1] = c;
    }
    __syncthreads();

    float cin = 0.0f;
#pragma unroll
    for (int s2 = 0; s2 < 7; s2++) {
        if (s2 < seg) {
            float P = smf[PS_W + (s2 * 64 + hc) * 2];
            float S = smf[PS_W + (s2 * 64 + hc) * 2 + 1];
            cin = fmaf(P, cin, S);
        }
    }

    {
        int gb = seg * 16 * GST + hc;
        float4* po = reinterpret_cast<float4*>(
            out + ((size_t)(b * HCv + hc) * Hv + h) * Wv + seg * 16);
        float hb[4];
#pragma unroll 2
        for (int j = 0; j < 16; j += 2) {
            float cp0 = smf[gb + 64],        fp0 = smf[gb + 192];
            float ov0 = smf[gb + 128];
            float cp1 = smf[gb + GST + 64],  fp1 = smf[gb + GST + 192];
            float ov1 = smf[gb + GST + 128];
            float t0 = fmaf(fp0, cin, cp0);
            float t1 = fmaf(fp1, cin, cp1);
            tanh2(t0, t1);
            hb[j & 3] = ov0 * t0;
            hb[(j & 3) + 1] = ov1 * t1;
            if ((j & 3) == 2)
                po[j >> 2] = make_float4(hb[0], hb[1], hb[2], hb[3]);
            gb += 2 * GST;
        }
    }
}

extern "C" void kernel_launch(void* const* d_in, const int* in_sizes, int n_in,
                              void* d_out, int out_size) {
    const float* x    = (const float*)d_in[0];
    const float* wgt  = (const float*)d_in[1];
    const float* bias = (const float*)d_in[2];
    float* out = (float*)d_out;

    cudaFuncSetAttribute(rowlstm_fused,
                         cudaFuncAttributeMaxDynamicSharedMemorySize, SMEM_BYTES);

    prep_w<<<192, 256>>>(wgt);
    prep_x<<<8192, 256>>>(x);
    rowlstm_fused<<<Bv * Hv, 512, SMEM_BYTES>>>(bias, out);
}

// round 8
// speedup vs baseline: 1.3595x; 1.3595x over previous
#include <cuda_runtime.h>
#include <cuda_fp16.h>
#include <cstdint>

#define Bv 16
#define Cv 64
#define Hv 128
#define Wv 128
#define HCv 64

// Pre-baked W image (fp16): [chunk(3)][m(256)][k(64) octet-swizzled] = 96 KB
__device__ __align__(16) uint16_t g_wimg[3 * 256 * 64];
// Pre-rounded X plane (fp16), layout [b][ic][h][w]
#define XN ((size_t)Bv * Cv * Hv * Wv)
__device__ __align__(16) __half g_xhi[XN];

// ---- smem map (bytes) ----
// W resident: 3 x 32KB at 0 ; XBUF: 2 x 16KB at 98304 -> 131072
// after mainloop (aliased): gates fp32 [w(128)][260 words] + PS at word 33280
#define XBUF_B   98304
#define GST      260
#define PS_W     33280
#define SMEM_BYTES 137216

extern __shared__ uint32_t smw[];

__device__ __forceinline__ uint32_t smem_u32(const void* p) {
    uint32_t a;
    asm("{ .reg .u64 t; cvta.to.shared.u64 t, %1; cvt.u32.u64 %0, t; }"
        : "=r"(a) : "l"(p));
    return a;
}

__device__ __forceinline__ float rcp_fast(float d) {
    float r;
    asm("rcp.approx.ftz.f32 %0, %1;" : "=f"(r) : "f"(d));
    return r;
}

// paired sigmoid: one RCP for two values
__device__ __forceinline__ void sigmoid2(float& v0, float& v1) {
    float e0 = __expf(-v0);
    float e1 = __expf(-v1);
    float p0 = 1.0f + e0, p1 = 1.0f + e1;
    float r = rcp_fast(p0 * p1);
    v0 = p1 * r;
    v1 = p0 * r;
}
// paired tanh: one RCP for two values
__device__ __forceinline__ void tanh2(float& v0, float& v1) {
    float e0 = __expf(-2.0f * fabsf(v0));
    float e1 = __expf(-2.0f * fabsf(v1));
    float p0 = 1.0f + e0, p1 = 1.0f + e1;
    float r = rcp_fast(p0 * p1);
    float t0 = (1.0f - e0) * p1 * r;
    float t1 = (1.0f - e1) * p0 * r;
    v0 = (v0 < 0.0f) ? -t0 : t0;
    v1 = (v1 < 0.0f) ? -t1 : t1;
}

__device__ __forceinline__ void mma_f16(float* c, const uint32_t* a,
                                        uint32_t b0, uint32_t b1) {
    asm volatile(
        "mma.sync.aligned.m16n8k16.row.col.f32.f16.f16.f32 "
        "{%0,%1,%2,%3}, {%4,%5,%6,%7}, {%8,%9}, {%0,%1,%2,%3};\n"
        : "+f"(c[0]), "+f"(c[1]), "+f"(c[2]), "+f"(c[3])
        : "r"(a[0]), "r"(a[1]), "r"(a[2]), "r"(a[3]), "r"(b0), "r"(b1));
}

#define LDM4(R, addr) \
    asm volatile("ldmatrix.sync.aligned.m8n8.x4.shared.b16 {%0,%1,%2,%3}, [%4];" \
        : "=r"((R)[0]), "=r"((R)[1]), "=r"((R)[2]), "=r"((R)[3]) : "r"(addr))
#define LDM4T(R, addr) \
    asm volatile("ldmatrix.sync.aligned.m8n8.x4.trans.shared.b16 {%0,%1,%2,%3}, [%4];" \
        : "=r"((R)[0]), "=r"((R)[1]), "=r"((R)[2]), "=r"((R)[3]) : "r"(addr))
#define CPA16(dst, src) \
    asm volatile("cp.async.ca.shared.global [%0], [%1], 16;" :: "r"(dst), "l"(src))
#define CPA16Z(dst, src, sz) \
    asm volatile("cp.async.ca.shared.global [%0], [%1], 16, %2;" \
                 :: "r"(dst), "l"(src), "r"(sz))
#define CPA_COMMIT() asm volatile("cp.async.commit_group;" ::: "memory")
#define CPA_WAIT0()  asm volatile("cp.async.wait_group 0;" ::: "memory")

// ---------------------------------------------------------------- prep kernel
// All blocks: round 8 floats of x to fp16 plane. Blocks 0..191 additionally
// bake one k-column of the W image (k = blockIdx.x, m = threadIdx.x).
__global__ void __launch_bounds__(256)
prep_xw(const float* __restrict__ x, const float* __restrict__ wgt) {
    if (blockIdx.x < 192) {
        int k = blockIdx.x;
        int m = threadIdx.x;
        float v = wgt[m * 192 + k];
        int c = k >> 6, kl = k & 63, o = kl >> 3, e = kl & 7;
        g_wimg[c * 16384 + m * 64 + (((o ^ (m & 7)) << 3) + e)] =
            __half_as_ushort(__float2half_rn(v));
    }
    size_t i = ((size_t)blockIdx.x * 256 + threadIdx.x) * 8;
    float4 a = *reinterpret_cast<const float4*>(x + i);
    float4 c = *reinterpret_cast<const float4*>(x + i + 4);
    float vf[8] = {a.x, a.y, a.z, a.w, c.x, c.y, c.z, c.w};
    uint32_t hw[4];
#pragma unroll
    for (int j = 0; j < 4; j++) {
        __half2 hh = __float22half2_rn(make_float2(vf[2 * j], vf[2 * j + 1]));
        hw[j] = *reinterpret_cast<uint32_t*>(&hh);
    }
    *reinterpret_cast<uint4*>(g_xhi + i) = make_uint4(hw[0], hw[1], hw[2], hw[3]);
}

// ---------------------------------------------------------------- fused kernel
// One block per (b,h), 512 threads = 16 warps (4m x 4n), warp tile 64x32.
// W (96KB) smem-resident; X (fp16 plane) streamed per 64-k chunk via cp.async.
__global__ void __launch_bounds__(512, 1)
rowlstm_fused(const float* __restrict__ bias, float* __restrict__ out) {
    float* smf = reinterpret_cast<float*>(smw);
    const int tid = threadIdx.x;
    const int lane = tid & 31;
    const int wid = tid >> 5;
    const int mw = wid & 3;
    const int nw = wid >> 2;
    const int r = lane >> 2, cl = lane & 3;
    const int bh = blockIdx.x, b = bh >> 7, h = bh & 127;

    const uint32_t smb = smem_u32(smw);

    // ldmatrix lane params
    const int l7 = lane & 7, l15 = lane & 15, lk = lane >> 4;
    const int krl = l7 + ((lane & 16) >> 1);
    const int wo = (lane >> 3) & 1;

    uint64_t gw, gxh;
    asm("cvta.to.global.u64 %0, %1;" : "=l"(gw) : "l"((const void*)g_wimg));
    asm("cvta.to.global.u64 %0, %1;" : "=l"(gxh) : "l"((const void*)g_xhi));

    float acc[4][4][4];
#pragma unroll
    for (int mt = 0; mt < 4; mt++)
#pragma unroll
        for (int nt = 0; nt < 4; nt++)
#pragma unroll
            for (int q = 0; q < 4; q++) acc[mt][nt][q] = 0.0f;

// stage X chunk cn into buffer db: per thread 2 granules (1024 total = 16KB)
#define STAGE_X(cn, db)                                                     \
    do {                                                                    \
        _Pragma("unroll") for (int t = 0; t < 2; t++) {                     \
            int g = t * 512 + tid;                                          \
            int krow = g >> 4;                                              \
            int woct = g & 15;                                              \
            int kg = (cn) * 64 + krow;                                      \
            int ic = kg / 3;                                                \
            int kh = kg - 3 * ic;                                           \
            int hp = h + kh - 2;                                            \
            int sz = (hp >= 0) ? 16 : 0;                                    \
            int hpc = (hp >= 0) ? hp : 0;                                   \
            size_t eoff = (((size_t)(b * Cv + ic) * Hv + hpc) * Wv +        \
                           woct * 8) * 2;                                   \
            uint32_t dst = smb + XBUF_B + (db) * 16384 + krow * 256 +       \
                           ((woct ^ (krow & 7)) << 4);                      \
            CPA16Z(dst, gxh + eoff, sz);                                    \
        }                                                                   \
    } while (0)

    // ---- preamble: W (all 96KB) + X chunk 0
    {
#pragma unroll
        for (int j = 0; j < 12; j++)
            CPA16(smb + tid * 16 + j * 8192, gw + tid * 16 + j * 8192);
        STAGE_X(0, 0);
        CPA_COMMIT();
        CPA_WAIT0();
        __syncthreads();
    }

#pragma unroll
    for (int c = 0; c < 3; c++) {
        const int db = c & 1;
        if (c < 2) {
            STAGE_X(c + 1, db ^ 1);
            CPA_COMMIT();
        }

        const uint32_t a_h = smb + c * 32768 + (mw * 64 + l15) * 128;
        uint32_t bb[2];
#pragma unroll
        for (int np = 0; np < 2; np++) {
            int oct = ((nw * 32 + np * 16) >> 3) + wo;
            bb[np] = smb + XBUF_B + db * 16384 + krl * 256 + ((oct ^ l7) << 4);
        }
#pragma unroll
        for (int ks = 0; ks < 4; ks++) {
            uint32_t Bh[2][4];
#pragma unroll
            for (int np = 0; np < 2; np++)
                LDM4T(Bh[np], bb[np] + ks * 4096);
            const uint32_t swA = (uint32_t)(((2 * ks + lk) ^ l7) << 4);
#pragma unroll
            for (int mt = 0; mt < 4; mt++) {
                uint32_t A[4];
                LDM4(A, a_h + mt * 2048 + swA);
#pragma unroll
                for (int nt = 0; nt < 4; nt++) {
                    const int np = nt >> 1, ix = nt & 1;
                    mma_f16(acc[mt][nt], A, Bh[np][ix], Bh[np][2 + ix]);
                }
            }
        }

        if (c < 2) {
            CPA_WAIT0();
            __syncthreads();
        }
    }
    __syncthreads();  // stage buffers reusable (gates alias them)

    // ---- epilogue: bias + activation -> gates smem [w][260]
    const bool isg = (mw == 3);
#pragma unroll
    for (int mt = 0; mt < 4; mt++) {
        const int m0 = mw * 64 + mt * 16;
        const float blo = bias[m0 + r];
        const float bhi = bias[m0 + 8 + r];
#pragma unroll
        for (int nt = 0; nt < 4; nt++) {
            const int w0 = nw * 32 + nt * 8 + 2 * cl;
            float v0 = acc[mt][nt][0] + blo;
            float v1 = acc[mt][nt][1] + blo;
            float v2 = acc[mt][nt][2] + bhi;
            float v3 = acc[mt][nt][3] + bhi;
            if (isg) { tanh2(v0, v1); tanh2(v2, v3); }
            else     { sigmoid2(v0, v1); sigmoid2(v2, v3); }
            smf[(size_t)w0 * GST + m0 + r]           = v0;
            smf[(size_t)(w0 + 1) * GST + m0 + r]     = v1;
            smf[(size_t)w0 * GST + m0 + 8 + r]       = v2;
            smf[(size_t)(w0 + 1) * GST + m0 + 8 + r] = v3;
        }
    }
    __syncthreads();

    // ---- LSTM scan: 8 segments of 16 w, parallel linear recurrence
    const int seg = tid >> 6;
    const int hc = tid & 63;
    {
        int gb = seg * 16 * GST + hc;
        float c = 0.0f, P = 1.0f;
#pragma unroll 8
        for (int j = 0; j < 16; j++) {
            float iv = smf[gb];
            float fv = smf[gb + 64];
            float gv = smf[gb + 192];
            c = fmaf(fv, c, iv * gv);
            P *= fv;
            smf[gb + 64] = c;
            smf[gb + 192] = P;
            gb += GST;
        }
        smf[PS_W + (seg * 64 + hc) * 2] = P;
        smf[PS_W + (seg * 64 + hc) * 2 + 1] = c;
    }
    __syncthreads();

    float cin = 0.0f;
#pragma unroll
    for (int s2 = 0; s2 < 7; s2++) {
        if (s2 < seg) {
            float P = smf[PS_W + (s2 * 64 + hc) * 2];
            float S = smf[PS_W + (s2 * 64 + hc) * 2 + 1];
            cin = fmaf(P, cin, S);
        }
    }

    {
        int gb = seg * 16 * GST + hc;
        float4* po = reinterpret_cast<float4*>(
            out + ((size_t)(b * HCv + hc) * Hv + h) * Wv + seg * 16);
        float hb[4];
#pragma unroll 2
        for (int j = 0; j < 16; j += 2) {
            float cp0 = smf[gb + 64],        fp0 = smf[gb + 192];
            float ov0 = smf[gb + 128];
            float cp1 = smf[gb + GST + 64],  fp1 = smf[gb + GST + 192];
            float ov1 = smf[gb + GST + 128];
            float t0 = fmaf(fp0, cin, cp0);
            float t1 = fmaf(fp1, cin, cp1);
            tanh2(t0, t1);
            hb[j & 3] = ov0 * t0;
            hb[(j & 3) + 1] = ov1 * t1;
            if ((j & 3) == 2)
                po[j >> 2] = make_float4(hb[0], hb[1], hb[2], hb[3]);
            gb += 2 * GST;
        }
    }
}

extern "C" void kernel_launch(void* const* d_in, const int* in_sizes, int n_in,
                              void* d_out, int out_size) {
    const float* x    = (const float*)d_in[0];
    const float* wgt  = (const float*)d_in[1];
    const float* bias = (const float*)d_in[2];
    float* out = (float*)d_out;

    cudaFuncSetAttribute(rowlstm_fused,
                         cudaFuncAttributeMaxDynamicSharedMemorySize, SMEM_BYTES);

    prep_xw<<<8192, 256>>>(x, wgt);
    rowlstm_fused<<<Bv * Hv, 512, SMEM_BYTES>>>(bias, out);
}